// round 1
// baseline (speedup 1.0000x reference)
#include <cuda_runtime.h>
#include <math.h>

// ---------------------------------------------------------------------------
// Gated DeltaNet forward, fp32 baseline.
// B=2 T=2048 C=2048 H=16 DK=DV=128 K(conv)=4
// Inputs (metadata order):
// 0 x(2,2048,2048) 1 input_pos(2048,i32) 2 W_qkvz(2048,8192) 3 W_b(2048,16)
// 4 W_a(2048,16) 5 conv_w(6144,1,4) 6 norm_w(128) 7 W_out(2048,2048)
// 8 conv_state(2,6144,4) 9 recurrent_state(2,16,128,128)
// Output: (2,2048,2048) f32
// ---------------------------------------------------------------------------

#define BB 2
#define TT 2048
#define CC 2048
#define HH 16
#define DKV 128
#define CONVD 6144
#define QN 8192
#define MM (BB*TT)      // 4096

// scratch (device globals: allocation-free rule)
__device__ float g_qkvz[(size_t)MM * QN];          // 128 MB
__device__ float g_q[(size_t)BB*HH*TT*DKV];        // 32 MB
__device__ float g_k[(size_t)BB*HH*TT*DKV];
__device__ float g_v[(size_t)BB*HH*TT*DKV];
__device__ float g_alpha[(size_t)MM*HH];
__device__ float g_beta [(size_t)MM*HH];
__device__ float g_pre[(size_t)MM * CC];           // 32 MB

// ---------------------------------------------------------------------------
// Generic fp32 SGEMM: C[M,N] = A[M,K] * B[K,N], row-major.
// 128x128 tile, BK=16, 256 threads, 8x8 micro-tile.
// Requires M%128==0, N%128==0, K%16==0 (true for all uses here).
// ---------------------------------------------------------------------------
#define GBM 128
#define GBN 128
#define GBK 16

__global__ __launch_bounds__(256) void sgemm_kernel(
    const float* __restrict__ A, const float* __restrict__ B,
    float* __restrict__ C, int M, int N, int K)
{
    __shared__ float As[GBK][GBM];
    __shared__ float Bs[GBK][GBN];
    const int bx = blockIdx.x;   // N tile
    const int by = blockIdx.y;   // M tile
    const int tid = threadIdx.x;
    const int tx = tid & 15;
    const int ty = tid >> 4;

    const float* Ab = A + (size_t)by * GBM * K;
    const float* Bb = B + (size_t)bx * GBN;

    // A tile: 128 rows x 16 cols, one float4 per thread, two rows apart
    const int a_r = tid >> 2;          // 0..63
    const int a_c = (tid & 3) * 4;     // 0,4,8,12
    // B tile: 16 rows x 128 cols
    const int b_r = tid >> 5;          // 0..7
    const int b_c = (tid & 31) * 4;

    float acc[8][8];
#pragma unroll
    for (int i = 0; i < 8; i++)
#pragma unroll
        for (int j = 0; j < 8; j++) acc[i][j] = 0.f;

    for (int k0 = 0; k0 < K; k0 += GBK) {
        float4 av0 = *(const float4*)&Ab[(size_t)a_r * K + k0 + a_c];
        float4 av1 = *(const float4*)&Ab[(size_t)(a_r + 64) * K + k0 + a_c];
        float4 bv0 = *(const float4*)&Bb[(size_t)(k0 + b_r) * N + b_c];
        float4 bv1 = *(const float4*)&Bb[(size_t)(k0 + b_r + 8) * N + b_c];

        As[a_c + 0][a_r] = av0.x; As[a_c + 1][a_r] = av0.y;
        As[a_c + 2][a_r] = av0.z; As[a_c + 3][a_r] = av0.w;
        As[a_c + 0][a_r + 64] = av1.x; As[a_c + 1][a_r + 64] = av1.y;
        As[a_c + 2][a_r + 64] = av1.z; As[a_c + 3][a_r + 64] = av1.w;
        *(float4*)&Bs[b_r][b_c]     = bv0;
        *(float4*)&Bs[b_r + 8][b_c] = bv1;
        __syncthreads();

#pragma unroll
        for (int kk = 0; kk < GBK; kk++) {
            float af[8], bf[8];
            *(float4*)&af[0] = *(float4*)&As[kk][ty * 8];
            *(float4*)&af[4] = *(float4*)&As[kk][ty * 8 + 4];
            *(float4*)&bf[0] = *(float4*)&Bs[kk][tx * 8];
            *(float4*)&bf[4] = *(float4*)&Bs[kk][tx * 8 + 4];
#pragma unroll
            for (int i = 0; i < 8; i++)
#pragma unroll
                for (int j = 0; j < 8; j++)
                    acc[i][j] = fmaf(af[i], bf[j], acc[i][j]);
        }
        __syncthreads();
    }

    // write back
#pragma unroll
    for (int i = 0; i < 8; i++) {
        const size_t row = (size_t)by * GBM + ty * 8 + i;
        float4 v0 = make_float4(acc[i][0], acc[i][1], acc[i][2], acc[i][3]);
        float4 v1 = make_float4(acc[i][4], acc[i][5], acc[i][6], acc[i][7]);
        *(float4*)&C[row * N + bx * GBN + tx * 8]     = v0;
        *(float4*)&C[row * N + bx * GBN + tx * 8 + 4] = v1;
    }
}

// ---------------------------------------------------------------------------
// alpha = sigmoid(x @ W_a), beta = sigmoid(x @ W_b). One block per row.
// ---------------------------------------------------------------------------
__global__ __launch_bounds__(256) void ab_kernel(
    const float* __restrict__ x, const float* __restrict__ W_b,
    const float* __restrict__ W_a)
{
    __shared__ float xs[CC];
    const int row = blockIdx.x;
    const int tid = threadIdx.x;
    const float* xr = x + (size_t)row * CC;
    for (int i = tid; i < CC / 4; i += 256)
        ((float4*)xs)[i] = ((const float4*)xr)[i];
    __syncthreads();

    const int cidx = tid >> 3;   // 0..31
    const int p = tid & 7;
    const float* W;
    int col;
    if (cidx < 16) { W = W_b; col = cidx; }
    else           { W = W_a; col = cidx - 16; }

    float acc = 0.f;
    for (int k = p; k < CC; k += 8)
        acc = fmaf(xs[k], W[(size_t)k * HH + col], acc);
    acc += __shfl_down_sync(0xffffffffu, acc, 4, 8);
    acc += __shfl_down_sync(0xffffffffu, acc, 2, 8);
    acc += __shfl_down_sync(0xffffffffu, acc, 1, 8);
    if (p == 0) {
        float s = 1.f / (1.f + expf(-acc));
        if (cidx < 16) g_beta [(size_t)row * HH + col] = s;
        else           g_alpha[(size_t)row * HH + col] = s;
    }
}

// ---------------------------------------------------------------------------
// Depthwise causal conv (K=4) + SiLU + split into q/k/v with per-head L2 norm.
// grid: (T/16, 48, B), block: 128 threads (one per channel in the 128-group).
// q/k/v layouts: [B][H][T][128]
// ---------------------------------------------------------------------------
__global__ __launch_bounds__(128) void conv_silu_kernel(
    const float* __restrict__ conv_w, const float* __restrict__ conv_state,
    const int* __restrict__ input_pos)
{
    const int t0 = blockIdx.x * 16;
    const int g  = blockIdx.y;     // 0..47 channel group
    const int b  = blockIdx.z;
    const int c  = threadIdx.x;    // 0..127
    const int cg = g * 128 + c;    // global channel < 6144
    const float keep = (input_pos[0] == 0) ? 0.f : 1.f;

    __shared__ float tile[19][128];
    __shared__ float red[4];

    const float* base = g_qkvz + (size_t)b * TT * QN + cg;
#pragma unroll
    for (int r = 0; r < 19; r++) {
        int tg = t0 - 3 + r;
        float v;
        if (tg < 0) v = keep * conv_state[((size_t)b * CONVD + cg) * 4 + (tg + 4)];
        else        v = base[(size_t)tg * QN];
        tile[r][c] = v;
    }
    float4 w = *(const float4*)(conv_w + (size_t)cg * 4);
    __syncthreads();

    float* outb;
    int head;
    if (g < 16)      { outb = g_q; head = g; }
    else if (g < 32) { outb = g_k; head = g - 16; }
    else             { outb = g_v; head = g - 32; }
    const bool isqk = (g < 32);
    const int lane = c & 31, warp = c >> 5;

    for (int tl = 0; tl < 16; tl++) {
        float y = w.x * tile[tl][c] + w.y * tile[tl + 1][c]
                + w.z * tile[tl + 2][c] + w.w * tile[tl + 3][c];
        y = y / (1.f + expf(-y));    // SiLU
        if (isqk) {
            float ss = y * y;
#pragma unroll
            for (int o = 16; o > 0; o >>= 1)
                ss += __shfl_down_sync(0xffffffffu, ss, o);
            if (lane == 0) red[warp] = ss;
            __syncthreads();
            ss = red[0] + red[1] + red[2] + red[3];
            y = y / fmaxf(sqrtf(ss), 1e-12f);
            __syncthreads();   // red reused next tl
        }
        const int tg = t0 + tl;
        outb[(((size_t)(b * HH + head)) * TT + tg) * 128 + c] = y;
    }
}

// ---------------------------------------------------------------------------
// Recurrent scan + RMSNorm + sigmoid(z) gate, fused.
// grid: B*H = 32 blocks, 128 threads. Thread j owns state column S[0..127][j]
// in registers. out uses the *post-update* state.
// ---------------------------------------------------------------------------
__global__ __launch_bounds__(128) void attn_scan_kernel(
    const float* __restrict__ rstate, const int* __restrict__ input_pos,
    const float* __restrict__ norm_w)
{
    const int bh = blockIdx.x;
    const int b = bh >> 4, h = bh & 15;
    const int j = threadIdx.x;
    const float keep = (input_pos[0] == 0) ? 0.f : 1.f;

    float S[128];
    const float* rs = rstate + ((size_t)bh * 128) * 128 + j;
#pragma unroll
    for (int i = 0; i < 128; i++) S[i] = keep * rs[(size_t)i * 128];

    __shared__ float qs[128], ks[128];
    __shared__ float red[4];
    const float nw = norm_w[j];

    const float* qp = g_q + ((size_t)bh * TT) * 128 + j;
    const float* kp = g_k + ((size_t)bh * TT) * 128 + j;
    const float* vp = g_v + ((size_t)bh * TT) * 128 + j;
    const float* zp = g_qkvz + (size_t)b * TT * QN + CONVD + h * 128 + j;
    const float* ap = g_alpha + (size_t)b * TT * HH + h;
    const float* bp = g_beta  + (size_t)b * TT * HH + h;
    float* op = g_pre + (size_t)b * TT * CC + h * 128 + j;

    // prefetch t=0
    float qc = qp[0], kc = kp[0], vc = vp[0], zc = zp[0], ac = ap[0], bc = bp[0];
    const int lane = j & 31, warp = j >> 5;

    for (int t = 0; t < TT; t++) {
        qs[j] = qc; ks[j] = kc;
        const float vcur = vc, acur = ac, bcur = bc, zcur = zc;
        __syncthreads();
        if (t < TT - 1) {   // prefetch next step (hidden under compute)
            qc = qp[(size_t)(t + 1) * 128];
            kc = kp[(size_t)(t + 1) * 128];
            vc = vp[(size_t)(t + 1) * 128];
            zc = zp[(size_t)(t + 1) * QN];
            ac = ap[(size_t)(t + 1) * HH];
            bc = bp[(size_t)(t + 1) * HH];
        }
        const float bv = bcur * vcur;
        float a0 = 0.f, a1 = 0.f, a2 = 0.f, a3 = 0.f;
#pragma unroll
        for (int i4 = 0; i4 < 32; i4++) {
            float4 q4 = *(const float4*)(qs + i4 * 4);
            float4 k4 = *(const float4*)(ks + i4 * 4);
            float s;
            s = fmaf(acur, S[i4*4+0], bv * k4.x); S[i4*4+0] = s; a0 = fmaf(q4.x, s, a0);
            s = fmaf(acur, S[i4*4+1], bv * k4.y); S[i4*4+1] = s; a1 = fmaf(q4.y, s, a1);
            s = fmaf(acur, S[i4*4+2], bv * k4.z); S[i4*4+2] = s; a2 = fmaf(q4.z, s, a2);
            s = fmaf(acur, S[i4*4+3], bv * k4.w); S[i4*4+3] = s; a3 = fmaf(q4.w, s, a3);
        }
        float out = (a0 + a1) + (a2 + a3);

        // RMSNorm over the 128 columns of this (b,t,h)
        float ss = out * out;
#pragma unroll
        for (int o = 16; o > 0; o >>= 1)
            ss += __shfl_down_sync(0xffffffffu, ss, o);
        if (lane == 0) red[warp] = ss;
        __syncthreads();
        ss = red[0] + red[1] + red[2] + red[3];
        const float inv = rsqrtf(ss * (1.f / 128.f) + 1e-6f);
        float res = out * inv * nw;
        res = res / (1.f + expf(-zcur));   // * sigmoid(z)
        op[(size_t)t * CC] = res;
    }
}

// ---------------------------------------------------------------------------
extern "C" void kernel_launch(void* const* d_in, const int* in_sizes, int n_in,
                              void* d_out, int out_size)
{
    const float* x        = (const float*)d_in[0];
    const int*   ipos     = (const int*)  d_in[1];
    const float* W_qkvz   = (const float*)d_in[2];
    const float* W_b      = (const float*)d_in[3];
    const float* W_a      = (const float*)d_in[4];
    const float* conv_w   = (const float*)d_in[5];
    const float* norm_w   = (const float*)d_in[6];
    const float* W_out    = (const float*)d_in[7];
    const float* cstate   = (const float*)d_in[8];
    const float* rstate   = (const float*)d_in[9];
    float* out = (float*)d_out;

    float *p_qkvz, *p_pre;
    cudaGetSymbolAddress((void**)&p_qkvz, g_qkvz);
    cudaGetSymbolAddress((void**)&p_pre,  g_pre);

    // 1) qkvz = x @ W_qkvz   (4096 x 8192, K=2048)
    sgemm_kernel<<<dim3(QN / GBN, MM / GBM), 256>>>(x, W_qkvz, p_qkvz, MM, QN, CC);

    // 2) alpha/beta
    ab_kernel<<<MM, 256>>>(x, W_b, W_a);

    // 3) conv + silu + l2norm -> q,k,v
    conv_silu_kernel<<<dim3(TT / 16, 48, BB), 128>>>(conv_w, cstate, ipos);

    // 4) recurrent scan + rmsnorm + gate -> pre
    attn_scan_kernel<<<BB * HH, 128>>>(rstate, ipos, norm_w);

    // 5) out = pre @ W_out   (4096 x 2048, K=2048)
    sgemm_kernel<<<dim3(CC / GBN, MM / GBM), 256>>>(p_pre, W_out, out, MM, CC, CC);
}

// round 2
// speedup vs baseline: 1.9264x; 1.9264x over previous
#include <cuda_runtime.h>
#include <math.h>
#include <stdint.h>

// ---------------------------------------------------------------------------
// Gated DeltaNet forward. B=2 T=2048 C=2048 H=16 DK=DV=128 K(conv)=4
// Round 2: TF32 tensor-core GEMMs + 4x-split scan + separate norm/gate kernel.
// ---------------------------------------------------------------------------

#define BB 2
#define TT 2048
#define CC 2048
#define HH 16
#define CONVD 6144
#define QN 8192
#define MM (BB*TT)      // 4096

// scratch (device globals: allocation-free rule)
__device__ float g_qkvz[(size_t)MM * QN];          // 128 MB
__device__ float g_q[(size_t)BB*HH*TT*128];        // 32 MB
__device__ float g_k[(size_t)BB*HH*TT*128];
__device__ float g_v[(size_t)BB*HH*TT*128];
__device__ float g_alpha[(size_t)MM*HH];
__device__ float g_beta [(size_t)MM*HH];
__device__ float g_pre[(size_t)MM * CC];           // 32 MB

// ---------------------------------------------------------------------------
// TF32 tensor-core GEMM: C[M,N] = A[M,K] * B[K,N], row-major f32 in/out.
// CTA 128x128, BK=32, 256 threads (8 warps, 2x4), warp tile 64x32 via
// mma.sync.m16n8k8.tf32. cp.async double buffer. M%128==N%128==0, K%32==0.
// ---------------------------------------------------------------------------

__device__ __forceinline__ void cpasync16(float* sptr, const float* gptr) {
    uint32_t s = (uint32_t)__cvta_generic_to_shared(sptr);
    asm volatile("cp.async.cg.shared.global [%0], [%1], 16;\n" :: "r"(s), "l"(gptr));
}
__device__ __forceinline__ uint32_t f2tf(float x) {
    uint32_t r; asm("cvt.rna.tf32.f32 %0, %1;\n" : "=r"(r) : "f"(x)); return r;
}
__device__ __forceinline__ void mma_tf32(float* c,
    uint32_t a0, uint32_t a1, uint32_t a2, uint32_t a3, uint32_t b0, uint32_t b1)
{
    asm volatile(
        "mma.sync.aligned.m16n8k8.row.col.f32.tf32.tf32.f32 "
        "{%0,%1,%2,%3}, {%4,%5,%6,%7}, {%8,%9}, {%0,%1,%2,%3};\n"
        : "+f"(c[0]), "+f"(c[1]), "+f"(c[2]), "+f"(c[3])
        : "r"(a0), "r"(a1), "r"(a2), "r"(a3), "r"(b0), "r"(b1));
}

#define AS_STRIDE 36      // 32 + 4 pad : bank = 4m+k  (conflict-free frag loads)
#define BS_STRIDE 136     // 128 + 8 pad: bank = 8k+n  (conflict-free frag loads)
#define AS_BUF (128*AS_STRIDE)   // floats per buffer
#define BS_BUF (32*BS_STRIDE)
#define SMEM_FLOATS (2*AS_BUF + 2*BS_BUF)   // 17920 floats = 71680 B

extern __shared__ float smem_dyn[];

__global__ void __launch_bounds__(256, 2) sgemm_tf32_kernel(
    const float* __restrict__ A, const float* __restrict__ B,
    float* __restrict__ C, int M, int N, int K)
{
    float* As = smem_dyn;                 // [2][128][36]
    float* Bs = smem_dyn + 2 * AS_BUF;    // [2][32][136]

    const int tid = threadIdx.x;
    const int bx = blockIdx.x, by = blockIdx.y;
    const int wid = tid >> 5, l = tid & 31;
    const int wm = (wid & 1) * 64;        // warp row offset
    const int wn = (wid >> 1) * 32;       // warp col offset
    const int lg = l >> 2, lt = l & 3;

    const float* Ab = A + (size_t)by * 128 * K;
    const float* Bb = B + (size_t)bx * 128;

    const int arow = tid >> 1, acol = (tid & 1) * 16;   // 64B per thread
    const int brow = tid >> 3, bcol = (tid & 7) * 16;

    float acc[4][4][4];
#pragma unroll
    for (int mt = 0; mt < 4; mt++)
#pragma unroll
        for (int nt = 0; nt < 4; nt++)
#pragma unroll
            for (int i = 0; i < 4; i++) acc[mt][nt][i] = 0.f;

    auto load_tile = [&](int it, int buf) {
        const float* ag = Ab + (size_t)arow * K + it * 32 + acol;
        float* asd = As + buf * AS_BUF + arow * AS_STRIDE + acol;
#pragma unroll
        for (int i = 0; i < 4; i++) cpasync16(asd + i * 4, ag + i * 4);
        const float* bg = Bb + (size_t)(it * 32 + brow) * N + bcol;
        float* bsd = Bs + buf * BS_BUF + brow * BS_STRIDE + bcol;
#pragma unroll
        for (int i = 0; i < 4; i++) cpasync16(bsd + i * 4, bg + i * 4);
        asm volatile("cp.async.commit_group;\n");
    };

    load_tile(0, 0);
    asm volatile("cp.async.wait_group 0;\n");
    __syncthreads();

    const int niter = K / 32;
    for (int it = 0; it < niter; it++) {
        const int buf = it & 1;
        if (it + 1 < niter) load_tile(it + 1, (it + 1) & 1);

        const float* Asb = As + buf * AS_BUF;
        const float* Bsb = Bs + buf * BS_BUF;
#pragma unroll
        for (int kk = 0; kk < 32; kk += 8) {
            uint32_t bb0[4], bb1[4];
#pragma unroll
            for (int nt = 0; nt < 4; nt++) {
                const int nb = wn + nt * 8 + lg;
                bb0[nt] = f2tf(Bsb[(kk + lt) * BS_STRIDE + nb]);
                bb1[nt] = f2tf(Bsb[(kk + 4 + lt) * BS_STRIDE + nb]);
            }
#pragma unroll
            for (int mt = 0; mt < 4; mt++) {
                const int rb = wm + mt * 16 + lg;
                uint32_t a0 = f2tf(Asb[rb * AS_STRIDE + kk + lt]);
                uint32_t a1 = f2tf(Asb[(rb + 8) * AS_STRIDE + kk + lt]);
                uint32_t a2 = f2tf(Asb[rb * AS_STRIDE + kk + 4 + lt]);
                uint32_t a3 = f2tf(Asb[(rb + 8) * AS_STRIDE + kk + 4 + lt]);
#pragma unroll
                for (int nt = 0; nt < 4; nt++)
                    mma_tf32(acc[mt][nt], a0, a1, a2, a3, bb0[nt], bb1[nt]);
            }
        }
        asm volatile("cp.async.wait_group 0;\n");
        __syncthreads();
    }

    // epilogue: c0,c1 at (row, 2*lt), c2,c3 at (row+8, 2*lt)
#pragma unroll
    for (int mt = 0; mt < 4; mt++) {
        const int r0 = by * 128 + wm + mt * 16 + lg;
#pragma unroll
        for (int nt = 0; nt < 4; nt++) {
            const int c0 = bx * 128 + wn + nt * 8 + lt * 2;
            *(float2*)&C[(size_t)r0 * N + c0]       = make_float2(acc[mt][nt][0], acc[mt][nt][1]);
            *(float2*)&C[(size_t)(r0 + 8) * N + c0] = make_float2(acc[mt][nt][2], acc[mt][nt][3]);
        }
    }
}

// ---------------------------------------------------------------------------
// alpha = sigmoid(x @ W_a), beta = sigmoid(x @ W_b). One block per row.
// ---------------------------------------------------------------------------
__global__ __launch_bounds__(256) void ab_kernel(
    const float* __restrict__ x, const float* __restrict__ W_b,
    const float* __restrict__ W_a)
{
    __shared__ float xs[CC];
    const int row = blockIdx.x;
    const int tid = threadIdx.x;
    const float* xr = x + (size_t)row * CC;
    for (int i = tid; i < CC / 4; i += 256)
        ((float4*)xs)[i] = ((const float4*)xr)[i];
    __syncthreads();

    const int cidx = tid >> 3;   // 0..31
    const int p = tid & 7;
    const float* W;
    int col;
    if (cidx < 16) { W = W_b; col = cidx; }
    else           { W = W_a; col = cidx - 16; }

    float acc = 0.f;
    for (int k = p; k < CC; k += 8)
        acc = fmaf(xs[k], W[(size_t)k * HH + col], acc);
    acc += __shfl_down_sync(0xffffffffu, acc, 4, 8);
    acc += __shfl_down_sync(0xffffffffu, acc, 2, 8);
    acc += __shfl_down_sync(0xffffffffu, acc, 1, 8);
    if (p == 0) {
        float s = 1.f / (1.f + expf(-acc));
        if (cidx < 16) g_beta [(size_t)row * HH + col] = s;
        else           g_alpha[(size_t)row * HH + col] = s;
    }
}

// ---------------------------------------------------------------------------
// Depthwise causal conv (K=4) + SiLU + split into q/k/v with per-head L2 norm.
// grid: (T/16, 48, B), block: 128. q/k/v layouts: [B][H][T][128]
// ---------------------------------------------------------------------------
__global__ __launch_bounds__(128) void conv_silu_kernel(
    const float* __restrict__ conv_w, const float* __restrict__ conv_state,
    const int* __restrict__ input_pos)
{
    const int t0 = blockIdx.x * 16;
    const int g  = blockIdx.y;     // 0..47 channel group
    const int b  = blockIdx.z;
    const int c  = threadIdx.x;    // 0..127
    const int cg = g * 128 + c;    // global channel < 6144
    const float keep = (input_pos[0] == 0) ? 0.f : 1.f;

    __shared__ float tile[19][128];
    __shared__ float red[4];

    const float* base = g_qkvz + (size_t)b * TT * QN + cg;
#pragma unroll
    for (int r = 0; r < 19; r++) {
        int tg = t0 - 3 + r;
        float v;
        if (tg < 0) v = keep * conv_state[((size_t)b * CONVD + cg) * 4 + (tg + 4)];
        else        v = base[(size_t)tg * QN];
        tile[r][c] = v;
    }
    float4 w = *(const float4*)(conv_w + (size_t)cg * 4);
    __syncthreads();

    float* outb;
    int head;
    if (g < 16)      { outb = g_q; head = g; }
    else if (g < 32) { outb = g_k; head = g - 16; }
    else             { outb = g_v; head = g - 32; }
    const bool isqk = (g < 32);
    const int lane = c & 31, warp = c >> 5;

    for (int tl = 0; tl < 16; tl++) {
        float y = w.x * tile[tl][c] + w.y * tile[tl + 1][c]
                + w.z * tile[tl + 2][c] + w.w * tile[tl + 3][c];
        y = y / (1.f + expf(-y));    // SiLU
        if (isqk) {
            float ss = y * y;
#pragma unroll
            for (int o = 16; o > 0; o >>= 1)
                ss += __shfl_down_sync(0xffffffffu, ss, o);
            if (lane == 0) red[warp] = ss;
            __syncthreads();
            ss = red[0] + red[1] + red[2] + red[3];
            y = y / fmaxf(sqrtf(ss), 1e-12f);
            __syncthreads();
        }
        const int tg = t0 + tl;
        outb[(((size_t)(b * HH + head)) * TT + tg) * 128 + c] = y;
    }
}

// ---------------------------------------------------------------------------
// Recurrent scan, split 4x over v-columns (columns of S are independent).
// grid: 128 blocks (bh*4 + jg), 128 threads: j = jg*32 + t/4, quarter = t&3.
// Thread holds 32 S-rows (dk = quarter*32 + i) of its column.
// Writes PRE-NORM output to g_pre; norm/gate done in normgate_kernel.
// ---------------------------------------------------------------------------
__global__ __launch_bounds__(128) void attn_scan_kernel(
    const float* __restrict__ rstate, const int* __restrict__ input_pos)
{
    const int bx = blockIdx.x;
    const int bh = bx >> 2, jg = bx & 3;
    const int b = bh >> 4, h = bh & 15;
    const int t = threadIdx.x;
    const int jl = t >> 2;           // 0..31
    const int quarter = t & 3;
    const int j = jg * 32 + jl;
    const float keep = (input_pos[0] == 0) ? 0.f : 1.f;

    float S[32];
    const float* rs = rstate + ((size_t)bh * 128) * 128 + j;
#pragma unroll
    for (int i = 0; i < 32; i++)
        S[i] = keep * rs[(size_t)(quarter * 32 + i) * 128];

    __shared__ __align__(16) float qs[4 * 36], ks[4 * 36];

    const float* qp = g_q + ((size_t)bh * TT) * 128;
    const float* kp = g_k + ((size_t)bh * TT) * 128;
    const float* vp = g_v + ((size_t)bh * TT) * 128;
    const float* ap = g_alpha + (size_t)b * TT * HH + h;
    const float* bp = g_beta  + (size_t)b * TT * HH + h;
    float* op = g_pre + (size_t)b * TT * CC + h * 128 + j;

    const int smi = (t >> 5) * 36 + (t & 31);

    // prefetch t=0
    float qc = qp[t], kc = kp[t], vc = vp[j], ac = ap[0], bc = bp[0];

    for (int tt = 0; tt < TT; tt++) {
        qs[smi] = qc; ks[smi] = kc;
        const float vcur = vc, acur = ac, bcur = bc;
        __syncthreads();
        if (tt < TT - 1) {
            qc = qp[(size_t)(tt + 1) * 128 + t];
            kc = kp[(size_t)(tt + 1) * 128 + t];
            vc = vp[(size_t)(tt + 1) * 128 + j];
            ac = ap[(size_t)(tt + 1) * HH];
            bc = bp[(size_t)(tt + 1) * HH];
        }
        const float bv = bcur * vcur;
        const float* qq = qs + quarter * 36;
        const float* kq = ks + quarter * 36;
        float a0 = 0.f, a1 = 0.f, a2 = 0.f, a3 = 0.f;
#pragma unroll
        for (int i4 = 0; i4 < 8; i4++) {
            float4 q4 = *(const float4*)(qq + i4 * 4);
            float4 k4 = *(const float4*)(kq + i4 * 4);
            float s;
            s = fmaf(acur, S[i4*4+0], bv * k4.x); S[i4*4+0] = s; a0 = fmaf(q4.x, s, a0);
            s = fmaf(acur, S[i4*4+1], bv * k4.y); S[i4*4+1] = s; a1 = fmaf(q4.y, s, a1);
            s = fmaf(acur, S[i4*4+2], bv * k4.z); S[i4*4+2] = s; a2 = fmaf(q4.z, s, a2);
            s = fmaf(acur, S[i4*4+3], bv * k4.w); S[i4*4+3] = s; a3 = fmaf(q4.w, s, a3);
        }
        float acc = (a0 + a1) + (a2 + a3);
        acc += __shfl_down_sync(0xffffffffu, acc, 2, 4);
        acc += __shfl_down_sync(0xffffffffu, acc, 1, 4);
        if (quarter == 0) op[(size_t)tt * CC] = acc;
        __syncthreads();
    }
}

// ---------------------------------------------------------------------------
// RMSNorm over DV=128 + norm_w + sigmoid(z) gate, in place on g_pre.
// One warp per (b,t,h): grid = MM*HH/8 blocks of 256 (8 warps).
// ---------------------------------------------------------------------------
__global__ __launch_bounds__(256) void normgate_kernel(
    const float* __restrict__ norm_w)
{
    const int gw = blockIdx.x * 8 + (threadIdx.x >> 5);  // 0..65535
    const int r = gw >> 4;      // b*TT + t
    const int h = gw & 15;
    const int l = threadIdx.x & 31;

    float* p = g_pre + (size_t)r * CC + h * 128;
    const float* zp = g_qkvz + (size_t)r * QN + CONVD + h * 128;

    float4 v = *(const float4*)(p + l * 4);
    float ss = v.x*v.x + v.y*v.y + v.z*v.z + v.w*v.w;
#pragma unroll
    for (int o = 16; o > 0; o >>= 1)
        ss += __shfl_xor_sync(0xffffffffu, ss, o);
    const float inv = rsqrtf(ss * (1.f / 128.f) + 1e-6f);

    float4 z4 = *(const float4*)(zp + l * 4);
    float4 w4 = *(const float4*)(norm_w + l * 4);
    float4 o4;
    o4.x = v.x * inv * w4.x / (1.f + expf(-z4.x));
    o4.y = v.y * inv * w4.y / (1.f + expf(-z4.y));
    o4.z = v.z * inv * w4.z / (1.f + expf(-z4.z));
    o4.w = v.w * inv * w4.w / (1.f + expf(-z4.w));
    *(float4*)(p + l * 4) = o4;
}

// ---------------------------------------------------------------------------
extern "C" void kernel_launch(void* const* d_in, const int* in_sizes, int n_in,
                              void* d_out, int out_size)
{
    const float* x        = (const float*)d_in[0];
    const int*   ipos     = (const int*)  d_in[1];
    const float* W_qkvz   = (const float*)d_in[2];
    const float* W_b      = (const float*)d_in[3];
    const float* W_a      = (const float*)d_in[4];
    const float* conv_w   = (const float*)d_in[5];
    const float* norm_w   = (const float*)d_in[6];
    const float* W_out    = (const float*)d_in[7];
    const float* cstate   = (const float*)d_in[8];
    const float* rstate   = (const float*)d_in[9];
    float* out = (float*)d_out;

    float *p_qkvz, *p_pre;
    cudaGetSymbolAddress((void**)&p_qkvz, g_qkvz);
    cudaGetSymbolAddress((void**)&p_pre,  g_pre);

    const int smem_bytes = SMEM_FLOATS * 4;   // 71680
    cudaFuncSetAttribute(sgemm_tf32_kernel,
                         cudaFuncAttributeMaxDynamicSharedMemorySize, smem_bytes);

    // 1) qkvz = x @ W_qkvz   (4096 x 8192, K=2048)
    sgemm_tf32_kernel<<<dim3(QN / 128, MM / 128), 256, smem_bytes>>>(
        x, W_qkvz, p_qkvz, MM, QN, CC);

    // 2) alpha/beta
    ab_kernel<<<MM, 256>>>(x, W_b, W_a);

    // 3) conv + silu + l2norm -> q,k,v
    conv_silu_kernel<<<dim3(TT / 16, 48, BB), 128>>>(conv_w, cstate, ipos);

    // 4) recurrent scan (pre-norm) -> pre
    attn_scan_kernel<<<BB * HH * 4, 128>>>(rstate, ipos);

    // 5) rmsnorm + gate in place
    normgate_kernel<<<MM * HH / 8, 256>>>(norm_w);

    // 6) out = pre @ W_out   (4096 x 2048, K=2048)
    sgemm_tf32_kernel<<<dim3(CC / 128, MM / 128), 256, smem_bytes>>>(
        p_pre, W_out, out, MM, CC, CC);
}

// round 4
// speedup vs baseline: 2.5799x; 1.3392x over previous
#include <cuda_runtime.h>
#include <cuda_fp16.h>
#include <math.h>
#include <stdint.h>

// ---------------------------------------------------------------------------
// Gated DeltaNet forward. B=2 T=2048 C=2048 H=16 DK=DV=128 K(conv)=4
// Round 4: fp16 mma.sync.m16n8k16 GEMMs (ldmatrix fragments), fp16 operands
// pre-converted once. sm_100 baseline ISA only (no tcgen05 on this toolchain).
// ---------------------------------------------------------------------------

#define BB 2
#define TT 2048
#define CC 2048
#define HH 16
#define CONVD 6144
#define QN 8192
#define MM (BB*TT)      // 4096

// scratch (device globals: allocation-free rule)
__device__ float  g_qkvz[(size_t)MM * QN];          // 128 MB
__device__ float  g_q[(size_t)BB*HH*TT*128];
__device__ float  g_k[(size_t)BB*HH*TT*128];
__device__ float  g_v[(size_t)BB*HH*TT*128];
__device__ float  g_alpha[(size_t)MM*HH];
__device__ float  g_beta [(size_t)MM*HH];
__device__ float  g_pre  [(size_t)MM * CC];         // scan output (f32)
__device__ __half g_xh   [(size_t)MM * CC];         // x in fp16
__device__ __half g_wqT  [(size_t)QN * CC];         // W_qkvz^T fp16 [8192][2048]
__device__ __half g_woT  [(size_t)CC * CC];         // W_out^T fp16
__device__ __half g_preh [(size_t)MM * CC];         // normgated pre in fp16

// ---------------------------------------------------------------------------
// PTX helpers
// ---------------------------------------------------------------------------
__device__ __forceinline__ uint32_t cvta_s(const void* p) {
    return (uint32_t)__cvta_generic_to_shared(p);
}
__device__ __forceinline__ void cpa16(uint32_t s, const void* g) {
    asm volatile("cp.async.cg.shared.global [%0], [%1], 16;\n" :: "r"(s), "l"(g));
}
__device__ __forceinline__ void cp_commit() {
    asm volatile("cp.async.commit_group;\n");
}
__device__ __forceinline__ void ldsm_x4(uint32_t* r, uint32_t addr) {
    asm volatile("ldmatrix.sync.aligned.m8n8.x4.shared.b16 {%0,%1,%2,%3}, [%4];\n"
                 : "=r"(r[0]), "=r"(r[1]), "=r"(r[2]), "=r"(r[3]) : "r"(addr));
}
__device__ __forceinline__ void mma_f16(float* c,
    uint32_t a0, uint32_t a1, uint32_t a2, uint32_t a3, uint32_t b0, uint32_t b1)
{
    asm volatile(
        "mma.sync.aligned.m16n8k16.row.col.f32.f16.f16.f32 "
        "{%0,%1,%2,%3}, {%4,%5,%6,%7}, {%8,%9}, {%0,%1,%2,%3};\n"
        : "+f"(c[0]), "+f"(c[1]), "+f"(c[2]), "+f"(c[3])
        : "r"(a0), "r"(a1), "r"(a2), "r"(a3), "r"(b0), "r"(b1));
}

// ---------------------------------------------------------------------------
// fp16 GEMM: C[M,N] = A[M,K] * Bt[N,K]^T.  A,Bt row-major fp16, C f32.
// CTA 128x128, K-tile 32, 256 thr (8 warps 2x4), warp tile 64x32.
// smem rows: 32 halves data in 40-half stride (80B) -> conflict-free LDSM.
// ---------------------------------------------------------------------------
#define HSTRIDE 40
#define HBUF (128*HSTRIDE)                 // halves per tile buffer
#define HBUF_B (HBUF*2)                    // 10240 bytes
#define GH_DYN (4*HBUF_B)                  // 40960 bytes

extern __shared__ __half hdyn[];

__global__ void __launch_bounds__(256, 2) gemm_f16_kernel(
    const __half* __restrict__ A, const __half* __restrict__ Bt,
    float* __restrict__ C, int M, int N, int K)
{
    const int tid = threadIdx.x;
    const int wid = tid >> 5, l = tid & 31;
    const int bx = blockIdx.x, by = blockIdx.y;   // bx: N tile, by: M tile
    const int wm = (wid & 1) * 64;
    const int wn = (wid >> 1) * 32;
    const int lg = l >> 2, lt = l & 3;
    const int li = l >> 3, lr = l & 7;

    const uint32_t sA = cvta_s(hdyn);              // A buf0, A buf1, B buf0, B buf1
    const uint32_t sB = sA + 2u * HBUF_B;

    const int row = tid >> 1;                      // 0..127
    const int ch  = (tid & 1) * 16;                // half offset 0/16
    const __half* agp = A  + (size_t)(by * 128 + row) * K + ch;
    const __half* bgp = Bt + (size_t)(bx * 128 + row) * K + ch;
    const uint32_t sdst = (uint32_t)(row * HSTRIDE + ch) * 2u;

    auto load_tile = [&](int it, int buf) {
        const __half* ag = agp + it * 32;
        const __half* bg = bgp + it * 32;
        const uint32_t ad = sA + (uint32_t)buf * HBUF_B + sdst;
        const uint32_t bd = sB + (uint32_t)buf * HBUF_B + sdst;
        cpa16(ad, ag); cpa16(ad + 16, ag + 8);
        cpa16(bd, bg); cpa16(bd + 16, bg + 8);
        cp_commit();
    };

    float acc[4][4][4];
#pragma unroll
    for (int mt = 0; mt < 4; mt++)
#pragma unroll
        for (int nt = 0; nt < 4; nt++)
#pragma unroll
            for (int i = 0; i < 4; i++) acc[mt][nt][i] = 0.f;

    // per-lane ldsm byte offsets (within a buffer)
    const uint32_t a_off = (uint32_t)((wm + (li & 1) * 8 + lr) * HSTRIDE + (li >> 1) * 8) * 2u;
    const uint32_t b_off = (uint32_t)((wn + (li >> 1) * 8 + lr) * HSTRIDE + (li & 1) * 8) * 2u;

    const int niter = K / 32;
    load_tile(0, 0);

    for (int it = 0; it < niter; it++) {
        const int buf = it & 1;
        if (it + 1 < niter) {
            load_tile(it + 1, 1 - buf);
            asm volatile("cp.async.wait_group 1;\n" ::: "memory");
        } else {
            asm volatile("cp.async.wait_group 0;\n" ::: "memory");
        }
        __syncthreads();

        const uint32_t ab = sA + (uint32_t)buf * HBUF_B;
        const uint32_t bb = sB + (uint32_t)buf * HBUF_B;
#pragma unroll
        for (int kk = 0; kk < 2; kk++) {           // two k16 slices
            uint32_t bf[4][2];
#pragma unroll
            for (int j = 0; j < 2; j++) {          // n-tile pairs
                uint32_t r[4];
                ldsm_x4(r, bb + b_off + (uint32_t)(j * 16 * HSTRIDE + kk * 16) * 2u);
                bf[2*j][0] = r[0]; bf[2*j][1] = r[1];
                bf[2*j+1][0] = r[2]; bf[2*j+1][1] = r[3];
            }
#pragma unroll
            for (int mt = 0; mt < 4; mt++) {
                uint32_t a[4];
                ldsm_x4(a, ab + a_off + (uint32_t)(mt * 16 * HSTRIDE + kk * 16) * 2u);
#pragma unroll
                for (int nt = 0; nt < 4; nt++)
                    mma_f16(acc[mt][nt], a[0], a[1], a[2], a[3], bf[nt][0], bf[nt][1]);
            }
        }
        __syncthreads();
    }

    // epilogue: c0,c1 at (row, 2lt), c2,c3 at (row+8, 2lt)
#pragma unroll
    for (int mt = 0; mt < 4; mt++) {
        const int r0 = by * 128 + wm + mt * 16 + lg;
#pragma unroll
        for (int nt = 0; nt < 4; nt++) {
            const int c0 = bx * 128 + wn + nt * 8 + lt * 2;
            *(float2*)&C[(size_t)r0 * N + c0]       = make_float2(acc[mt][nt][0], acc[mt][nt][1]);
            *(float2*)&C[(size_t)(r0 + 8) * N + c0] = make_float2(acc[mt][nt][2], acc[mt][nt][3]);
        }
    }
}

// ---------------------------------------------------------------------------
// prep: f32 -> f16 copy; f32 -> transposed f16
// ---------------------------------------------------------------------------
__global__ __launch_bounds__(256) void f2h_kernel(
    const float* __restrict__ in, __half* __restrict__ out, int n4)
{
    int i = blockIdx.x * 256 + threadIdx.x;
    const int stride = gridDim.x * 256;
    for (; i < n4; i += stride) {
        float4 v = ((const float4*)in)[i];
        __half2 h0 = __floats2half2_rn(v.x, v.y);
        __half2 h1 = __floats2half2_rn(v.z, v.w);
        ((uint2*)out)[i] = make_uint2(*(uint32_t*)&h0, *(uint32_t*)&h1);
    }
}

__global__ __launch_bounds__(256) void transpose_h_kernel(
    const float* __restrict__ in, __half* __restrict__ out, int R, int Cc)
{
    __shared__ float t[32][33];
    const int tx = threadIdx.x & 31, ty = threadIdx.x >> 5;   // 32x8
    const int c0 = blockIdx.x * 32, r0 = blockIdx.y * 32;
#pragma unroll
    for (int i = 0; i < 4; i++)
        t[ty + i * 8][tx] = in[(size_t)(r0 + ty + i * 8) * Cc + c0 + tx];
    __syncthreads();
#pragma unroll
    for (int i = 0; i < 4; i++)
        out[(size_t)(c0 + ty + i * 8) * R + r0 + tx] =
            __float2half_rn(t[tx][ty + i * 8]);
}

// ---------------------------------------------------------------------------
// alpha = sigmoid(x @ W_a), beta = sigmoid(x @ W_b). One block per row.
// ---------------------------------------------------------------------------
__global__ __launch_bounds__(256) void ab_kernel(
    const float* __restrict__ x, const float* __restrict__ W_b,
    const float* __restrict__ W_a)
{
    __shared__ float xs[CC];
    const int row = blockIdx.x;
    const int tid = threadIdx.x;
    const float* xr = x + (size_t)row * CC;
    for (int i = tid; i < CC / 4; i += 256)
        ((float4*)xs)[i] = ((const float4*)xr)[i];
    __syncthreads();

    const int cidx = tid >> 3;
    const int p = tid & 7;
    const float* W;
    int col;
    if (cidx < 16) { W = W_b; col = cidx; }
    else           { W = W_a; col = cidx - 16; }

    float acc = 0.f;
    for (int k = p; k < CC; k += 8)
        acc = fmaf(xs[k], W[(size_t)k * HH + col], acc);
    acc += __shfl_down_sync(0xffffffffu, acc, 4, 8);
    acc += __shfl_down_sync(0xffffffffu, acc, 2, 8);
    acc += __shfl_down_sync(0xffffffffu, acc, 1, 8);
    if (p == 0) {
        float s = 1.f / (1.f + expf(-acc));
        if (cidx < 16) g_beta [(size_t)row * HH + col] = s;
        else           g_alpha[(size_t)row * HH + col] = s;
    }
}

// ---------------------------------------------------------------------------
// Depthwise causal conv (K=4) + SiLU + q/k/v split with per-head L2 norm.
// ---------------------------------------------------------------------------
__global__ __launch_bounds__(128) void conv_silu_kernel(
    const float* __restrict__ conv_w, const float* __restrict__ conv_state,
    const int* __restrict__ input_pos)
{
    const int t0 = blockIdx.x * 16;
    const int g  = blockIdx.y;
    const int b  = blockIdx.z;
    const int c  = threadIdx.x;
    const int cg = g * 128 + c;
    const float keep = (input_pos[0] == 0) ? 0.f : 1.f;

    __shared__ float tile[19][128];
    __shared__ float red[4];

    const float* base = g_qkvz + (size_t)b * TT * QN + cg;
#pragma unroll
    for (int r = 0; r < 19; r++) {
        int tg = t0 - 3 + r;
        float v;
        if (tg < 0) v = keep * conv_state[((size_t)b * CONVD + cg) * 4 + (tg + 4)];
        else        v = base[(size_t)tg * QN];
        tile[r][c] = v;
    }
    float4 w = *(const float4*)(conv_w + (size_t)cg * 4);
    __syncthreads();

    float* outb;
    int head;
    if (g < 16)      { outb = g_q; head = g; }
    else if (g < 32) { outb = g_k; head = g - 16; }
    else             { outb = g_v; head = g - 32; }
    const bool isqk = (g < 32);
    const int lane = c & 31, warp = c >> 5;

    for (int tl = 0; tl < 16; tl++) {
        float y = w.x * tile[tl][c] + w.y * tile[tl + 1][c]
                + w.z * tile[tl + 2][c] + w.w * tile[tl + 3][c];
        y = y / (1.f + expf(-y));
        if (isqk) {
            float ss = y * y;
#pragma unroll
            for (int o = 16; o > 0; o >>= 1)
                ss += __shfl_down_sync(0xffffffffu, ss, o);
            if (lane == 0) red[warp] = ss;
            __syncthreads();
            ss = red[0] + red[1] + red[2] + red[3];
            y = y / fmaxf(sqrtf(ss), 1e-12f);
            __syncthreads();
        }
        const int tg = t0 + tl;
        outb[(((size_t)(b * HH + head)) * TT + tg) * 128 + c] = y;
    }
}

// ---------------------------------------------------------------------------
// Recurrent scan, split 4x over v-columns. Pre-norm output to g_pre.
// ---------------------------------------------------------------------------
__global__ __launch_bounds__(128) void attn_scan_kernel(
    const float* __restrict__ rstate, const int* __restrict__ input_pos)
{
    const int bx = blockIdx.x;
    const int bh = bx >> 2, jg = bx & 3;
    const int b = bh >> 4, h = bh & 15;
    const int t = threadIdx.x;
    const int jl = t >> 2;
    const int quarter = t & 3;
    const int j = jg * 32 + jl;
    const float keep = (input_pos[0] == 0) ? 0.f : 1.f;

    float S[32];
    const float* rs = rstate + ((size_t)bh * 128) * 128 + j;
#pragma unroll
    for (int i = 0; i < 32; i++)
        S[i] = keep * rs[(size_t)(quarter * 32 + i) * 128];

    __shared__ __align__(16) float qs[4 * 36], ks[4 * 36];

    const float* qp = g_q + ((size_t)bh * TT) * 128;
    const float* kp = g_k + ((size_t)bh * TT) * 128;
    const float* vp = g_v + ((size_t)bh * TT) * 128;
    const float* ap = g_alpha + (size_t)b * TT * HH + h;
    const float* bp = g_beta  + (size_t)b * TT * HH + h;
    float* op = g_pre + (size_t)b * TT * CC + h * 128 + j;

    const int smi = (t >> 5) * 36 + (t & 31);

    float qc = qp[t], kc = kp[t], vc = vp[j], ac = ap[0], bc = bp[0];

    for (int tt = 0; tt < TT; tt++) {
        qs[smi] = qc; ks[smi] = kc;
        const float vcur = vc, acur = ac, bcur = bc;
        __syncthreads();
        if (tt < TT - 1) {
            qc = qp[(size_t)(tt + 1) * 128 + t];
            kc = kp[(size_t)(tt + 1) * 128 + t];
            vc = vp[(size_t)(tt + 1) * 128 + j];
            ac = ap[(size_t)(tt + 1) * HH];
            bc = bp[(size_t)(tt + 1) * HH];
        }
        const float bv = bcur * vcur;
        const float* qq = qs + quarter * 36;
        const float* kq = ks + quarter * 36;
        float a0 = 0.f, a1 = 0.f, a2 = 0.f, a3 = 0.f;
#pragma unroll
        for (int i4 = 0; i4 < 8; i4++) {
            float4 q4 = *(const float4*)(qq + i4 * 4);
            float4 k4 = *(const float4*)(kq + i4 * 4);
            float s;
            s = fmaf(acur, S[i4*4+0], bv * k4.x); S[i4*4+0] = s; a0 = fmaf(q4.x, s, a0);
            s = fmaf(acur, S[i4*4+1], bv * k4.y); S[i4*4+1] = s; a1 = fmaf(q4.y, s, a1);
            s = fmaf(acur, S[i4*4+2], bv * k4.z); S[i4*4+2] = s; a2 = fmaf(q4.z, s, a2);
            s = fmaf(acur, S[i4*4+3], bv * k4.w); S[i4*4+3] = s; a3 = fmaf(q4.w, s, a3);
        }
        float acc = (a0 + a1) + (a2 + a3);
        acc += __shfl_down_sync(0xffffffffu, acc, 2, 4);
        acc += __shfl_down_sync(0xffffffffu, acc, 1, 4);
        if (quarter == 0) op[(size_t)tt * CC] = acc;
        __syncthreads();
    }
}

// ---------------------------------------------------------------------------
// RMSNorm + norm_w + sigmoid(z) gate -> fp16 g_preh (GEMM2 input).
// ---------------------------------------------------------------------------
__global__ __launch_bounds__(256) void normgate_kernel(
    const float* __restrict__ norm_w)
{
    const int gw = blockIdx.x * 8 + (threadIdx.x >> 5);
    const int r = gw >> 4;
    const int h = gw & 15;
    const int l = threadIdx.x & 31;

    const float* p = g_pre + (size_t)r * CC + h * 128;
    const float* zp = g_qkvz + (size_t)r * QN + CONVD + h * 128;
    __half* oh = g_preh + (size_t)r * CC + h * 128;

    float4 v = *(const float4*)(p + l * 4);
    float ss = v.x*v.x + v.y*v.y + v.z*v.z + v.w*v.w;
#pragma unroll
    for (int o = 16; o > 0; o >>= 1)
        ss += __shfl_xor_sync(0xffffffffu, ss, o);
    const float inv = rsqrtf(ss * (1.f / 128.f) + 1e-6f);

    float4 z4 = *(const float4*)(zp + l * 4);
    float4 w4 = *(const float4*)(norm_w + l * 4);
    float o0 = v.x * inv * w4.x / (1.f + expf(-z4.x));
    float o1 = v.y * inv * w4.y / (1.f + expf(-z4.y));
    float o2 = v.z * inv * w4.z / (1.f + expf(-z4.z));
    float o3 = v.w * inv * w4.w / (1.f + expf(-z4.w));
    __half2 h0 = __floats2half2_rn(o0, o1);
    __half2 h1 = __floats2half2_rn(o2, o3);
    *(uint2*)(oh + l * 4) = make_uint2(*(uint32_t*)&h0, *(uint32_t*)&h1);
}

// ---------------------------------------------------------------------------
extern "C" void kernel_launch(void* const* d_in, const int* in_sizes, int n_in,
                              void* d_out, int out_size)
{
    const float* x        = (const float*)d_in[0];
    const int*   ipos     = (const int*)  d_in[1];
    const float* W_qkvz   = (const float*)d_in[2];
    const float* W_b      = (const float*)d_in[3];
    const float* W_a      = (const float*)d_in[4];
    const float* conv_w   = (const float*)d_in[5];
    const float* norm_w   = (const float*)d_in[6];
    const float* W_out    = (const float*)d_in[7];
    const float* cstate   = (const float*)d_in[8];
    const float* rstate   = (const float*)d_in[9];
    float* out = (float*)d_out;

    float *p_qkvz, *p_pre;
    __half *p_xh, *p_wqT, *p_woT, *p_preh;
    cudaGetSymbolAddress((void**)&p_qkvz, g_qkvz);
    cudaGetSymbolAddress((void**)&p_pre,  g_pre);
    cudaGetSymbolAddress((void**)&p_xh,   g_xh);
    cudaGetSymbolAddress((void**)&p_wqT,  g_wqT);
    cudaGetSymbolAddress((void**)&p_woT,  g_woT);
    cudaGetSymbolAddress((void**)&p_preh, g_preh);

    static int smem_set = 0;
    if (!smem_set) {
        cudaFuncSetAttribute(gemm_f16_kernel,
                             cudaFuncAttributeMaxDynamicSharedMemorySize, GH_DYN);
        smem_set = 1;
    }

    // prep: convert x, transpose+convert weights to fp16
    f2h_kernel<<<512, 256>>>(x, p_xh, MM * CC / 4);
    transpose_h_kernel<<<dim3(QN / 32, CC / 32), 256>>>(W_qkvz, p_wqT, CC, QN);
    transpose_h_kernel<<<dim3(CC / 32, CC / 32), 256>>>(W_out,  p_woT, CC, CC);

    // 1) qkvz = x @ W_qkvz   (fp16 tensor cores)
    gemm_f16_kernel<<<dim3(QN / 128, MM / 128), 256, GH_DYN>>>(
        p_xh, p_wqT, p_qkvz, MM, QN, CC);

    // 2) alpha/beta
    ab_kernel<<<MM, 256>>>(x, W_b, W_a);

    // 3) conv + silu + l2norm -> q,k,v
    conv_silu_kernel<<<dim3(TT / 16, 48, BB), 128>>>(conv_w, cstate, ipos);

    // 4) recurrent scan (pre-norm) -> pre
    attn_scan_kernel<<<BB * HH * 4, 128>>>(rstate, ipos);

    // 5) rmsnorm + gate -> fp16 preh
    normgate_kernel<<<MM * HH / 8, 256>>>(norm_w);

    // 6) out = pre @ W_out   (fp16 tensor cores)
    gemm_f16_kernel<<<dim3(CC / 128, MM / 128), 256, GH_DYN>>>(
        p_preh, p_woT, out, MM, CC, CC);
}